// round 14
// baseline (speedup 1.0000x reference)
#include <cuda_runtime.h>
#include <cuda_bf16.h>
#include <math.h>

// DRR raycast, fused single kernel:
//   Block = 128 threads = 4 warps = 4 pixels.
//   Prologue: threads 0-3 compute per-pixel ray geometry + sample ranges -> smem.
//   Body: warp w samples pixel w (lanes stride sample axis, 2-stage pipelined
//   interior, fractions recomputed at consume to minimize live registers).
// Inputs (metadata order): volume[256^3] f32, k_inv[1,3,3], rt_inv[1,4,4],
//                          sdd[1], affine_inv[4,4], n_samples int32
// Output: f32 [1,200,200]

#define DRR_W 200
#define DRR_H 200
#define DRR_VOL 256
#define NPIX (DRR_W * DRR_H)

#define MAIN_TPB 128
#define PIX_PER_BLK 4

__device__ __forceinline__ void axis_clip(float p, float d, float lo_b, float hi_b,
                                          float& lo, float& hi) {
    if (fabsf(d) < 1e-12f) {
        if (p < lo_b || p > hi_b) { lo = 1.0f; hi = 0.0f; }
    } else {
        float r  = 1.0f / d;
        float ta = (lo_b - p) * r;
        float tb = (hi_b - p) * r;
        lo = fmaxf(lo, fminf(ta, tb));
        hi = fminf(hi, fmaxf(ta, tb));
    }
}

__device__ __forceinline__ float fetch_vox(const float* __restrict__ vol,
                                           int x, int y, int z) {
    if ((unsigned)x < (unsigned)DRR_VOL &&
        (unsigned)y < (unsigned)DRR_VOL &&
        (unsigned)z < (unsigned)DRR_VOL) {
        return __ldg(vol + (x << 16) + (y << 8) + z);
    }
    return 0.0f;
}

__device__ __forceinline__ float trilinear_guarded(const float* __restrict__ vol,
                                                   float x, float y, float z) {
    float fx = floorf(x), fy = floorf(y), fz = floorf(z);
    int ix = (int)fx, iy = (int)fy, iz = (int)fz;
    float ax = x - fx, ay = y - fy, az = z - fz;

    float c000 = fetch_vox(vol, ix,     iy,     iz);
    float c001 = fetch_vox(vol, ix,     iy,     iz + 1);
    float c010 = fetch_vox(vol, ix,     iy + 1, iz);
    float c011 = fetch_vox(vol, ix,     iy + 1, iz + 1);
    float c100 = fetch_vox(vol, ix + 1, iy,     iz);
    float c101 = fetch_vox(vol, ix + 1, iy,     iz + 1);
    float c110 = fetch_vox(vol, ix + 1, iy + 1, iz);
    float c111 = fetch_vox(vol, ix + 1, iy + 1, iz + 1);

    float c00 = fmaf(az, c001 - c000, c000);
    float c01 = fmaf(az, c011 - c010, c010);
    float c10 = fmaf(az, c101 - c100, c100);
    float c11 = fmaf(az, c111 - c110, c110);
    float c0  = fmaf(ay, c01 - c00, c00);
    float c1  = fmaf(ay, c11 - c10, c10);
    return fmaf(ax, c1 - c0, c0);
}

__global__ __launch_bounds__(MAIN_TPB, 13)
void drr_kernel(const float* __restrict__ vol,
                const float* __restrict__ k_inv,
                const float* __restrict__ rt_inv,
                const float* __restrict__ sdd_p,
                const float* __restrict__ aff,
                const int*   __restrict__ n_ptr,
                float* __restrict__ out) {
    __shared__ float4 s_gA[PIX_PER_BLK];   // {p0x, p0y, p0z, step}
    __shared__ float4 s_gB[PIX_PER_BLK];   // {ddx, ddy, ddz, 0}
    __shared__ int4   s_rng[PIX_PER_BLK];  // {s_lo, s_hi, A, B}

    int tid  = threadIdx.x;
    int lane = tid & 31;
    int wid  = tid >> 5;

    // ---------- Prologue: threads 0..3 compute geometry for the block's pixels ----------
    if (tid < PIX_PER_BLK) {
        int pix = blockIdx.x * PIX_PER_BLK + tid;
        int u = pix % DRR_W;
        int v = pix / DRR_W;

        int   n    = *n_ptr;
        float fn1  = (float)(n - 1);
        float invn = 1.0f / fn1;
        float sdd  = __ldg(sdd_p);
        float fu = (float)u, fv = (float)v;

        float tc0 = (__ldg(k_inv + 0) * fu + __ldg(k_inv + 1) * fv + __ldg(k_inv + 2)) * sdd;
        float tc1 = (__ldg(k_inv + 3) * fu + __ldg(k_inv + 4) * fv + __ldg(k_inv + 5)) * sdd;
        float tc2 = (__ldg(k_inv + 6) * fu + __ldg(k_inv + 7) * fv + __ldg(k_inv + 8)) * sdd;

        float ray0 = __ldg(rt_inv + 0) * tc0 + __ldg(rt_inv + 1) * tc1 + __ldg(rt_inv + 2)  * tc2;
        float ray1 = __ldg(rt_inv + 4) * tc0 + __ldg(rt_inv + 5) * tc1 + __ldg(rt_inv + 6)  * tc2;
        float ray2 = __ldg(rt_inv + 8) * tc0 + __ldg(rt_inv + 9) * tc1 + __ldg(rt_inv + 10) * tc2;
        float sx = __ldg(rt_inv + 3), sy = __ldg(rt_inv + 7), sz = __ldg(rt_inv + 11);

        float step = sqrtf(ray0 * ray0 + ray1 * ray1 + ray2 * ray2) * invn;

        float p0x = __ldg(aff + 0) * sx + __ldg(aff + 1) * sy + __ldg(aff + 2)  * sz + __ldg(aff + 3);
        float p0y = __ldg(aff + 4) * sx + __ldg(aff + 5) * sy + __ldg(aff + 6)  * sz + __ldg(aff + 7);
        float p0z = __ldg(aff + 8) * sx + __ldg(aff + 9) * sy + __ldg(aff + 10) * sz + __ldg(aff + 11);
        float dx  = __ldg(aff + 0) * ray0 + __ldg(aff + 1) * ray1 + __ldg(aff + 2)  * ray2;
        float dy  = __ldg(aff + 4) * ray0 + __ldg(aff + 5) * ray1 + __ldg(aff + 6)  * ray2;
        float dz  = __ldg(aff + 8) * ray0 + __ldg(aff + 9) * ray1 + __ldg(aff + 10) * ray2;

        float lo = 0.0f, hi = 1.0f;
        axis_clip(p0x, dx, -1.0f, (float)DRR_VOL, lo, hi);
        axis_clip(p0y, dy, -1.0f, (float)DRR_VOL, lo, hi);
        axis_clip(p0z, dz, -1.0f, (float)DRR_VOL, lo, hi);

        float li = 0.0f, hii = 1.0f;
        axis_clip(p0x, dx, 0.0f, 254.99f, li, hii);
        axis_clip(p0y, dy, 0.0f, 254.99f, li, hii);
        axis_clip(p0z, dz, 0.0f, 254.99f, li, hii);

        int s_lo, s_hi, A, B;
        if (lo <= hi) {
            s_lo = (int)floorf(lo * fn1) - 2;
            s_hi = (int)ceilf(hi * fn1) + 2;
            if (s_lo < 0) s_lo = 0;
            if (s_hi > n - 1) s_hi = n - 1;

            if (li <= hii) {
                A = (int)ceilf(li * fn1) + 1;
                B = (int)floorf(hii * fn1) - 1;
                if (A < s_lo) A = s_lo;
                if (B > s_hi) B = s_hi;
                if (B < A) { A = s_hi + 1; B = s_hi; }
            } else {
                A = s_hi + 1; B = s_hi;
            }
        } else {
            s_lo = 0; s_hi = -1; A = 1; B = 0;
        }

        s_gA[tid]  = make_float4(p0x, p0y, p0z, step);
        s_gB[tid]  = make_float4(dx * invn, dy * invn, dz * invn, 0.0f);
        s_rng[tid] = make_int4(s_lo, s_hi, A, B);
    }
    __syncthreads();

    // ---------- Body: warp `wid` samples its pixel ----------
    float4 ga = s_gA[wid];
    float4 gb = s_gB[wid];
    int4   rg = s_rng[wid];

    float p0x = ga.x, p0y = ga.y, p0z = ga.z, step = ga.w;
    float ddx = gb.x, ddy = gb.y, ddz = gb.z;
    int s_lo = rg.x, s_hi = rg.y, A = rg.z, B = rg.w;

    float acc = 0.0f;

    // --- Merged guarded boundary loop: head [s_lo, A-1] ++ tail [B+1, s_hi] ---
    {
        int headN = A - s_lo;
        int total = headN + (s_hi - B);
        #pragma unroll 1
        for (int k = lane; k < total; k += 32) {
            int s = (k < headN) ? (s_lo + k) : (B + 1 + (k - headN));
            float sf = (float)s;
            acc += trilinear_guarded(vol,
                                     fmaf(sf, ddx, p0x),
                                     fmaf(sf, ddy, p0y),
                                     fmaf(sf, ddz, p0z));
        }
    }

    // --- Unguarded interior [A, B], 2-stage pipeline, minimal live state ---
    {
        int s = A + lane;
        float sf;
        float c0v, c1v, c2v, c3v, c4v, c5v, c6v, c7v;

        bool have = (s <= B);
        if (have) {
            sf = (float)s;
            float x = fmaf(sf, ddx, p0x);
            float y = fmaf(sf, ddy, p0y);
            float z = fmaf(sf, ddz, p0z);
            int ix = __float2int_rd(x), iy = __float2int_rd(y), iz = __float2int_rd(z);
            const float* p = vol + (ix << 16) + (iy << 8) + iz;
            c0v = __ldg(p);         c1v = __ldg(p + 1);
            c2v = __ldg(p + 256);   c3v = __ldg(p + 257);
            c4v = __ldg(p + 65536); c5v = __ldg(p + 65537);
            c6v = __ldg(p + 65792); c7v = __ldg(p + 65793);
        }

        #pragma unroll 1
        while (s + 32 <= B) {
            // Prefetch next batch (independent of current lerp chain).
            float sfn = sf + 32.0f;
            float xn = fmaf(sfn, ddx, p0x);
            float yn = fmaf(sfn, ddy, p0y);
            float zn = fmaf(sfn, ddz, p0z);
            int ixn = __float2int_rd(xn), iyn = __float2int_rd(yn), izn = __float2int_rd(zn);
            const float* pn = vol + (ixn << 16) + (iyn << 8) + izn;
            float n0 = __ldg(pn);         float n1 = __ldg(pn + 1);
            float n2 = __ldg(pn + 256);   float n3 = __ldg(pn + 257);
            float n4 = __ldg(pn + 65536); float n5 = __ldg(pn + 65537);
            float n6 = __ldg(pn + 65792); float n7 = __ldg(pn + 65793);

            // Consume current batch; fractions recomputed from sf.
            float xc = fmaf(sf, ddx, p0x);
            float yc = fmaf(sf, ddy, p0y);
            float zc = fmaf(sf, ddz, p0z);
            float ax = xc - floorf(xc);
            float ay = yc - floorf(yc);
            float az = zc - floorf(zc);

            float c00 = fmaf(az, c1v - c0v, c0v);
            float c01 = fmaf(az, c3v - c2v, c2v);
            float c10 = fmaf(az, c5v - c4v, c4v);
            float c11 = fmaf(az, c7v - c6v, c6v);
            float cc0 = fmaf(ay, c01 - c00, c00);
            float cc1 = fmaf(ay, c11 - c10, c10);
            acc += fmaf(ax, cc1 - cc0, cc0);

            // Rotate pipeline.
            sf = sfn;
            c0v = n0; c1v = n1; c2v = n2; c3v = n3;
            c4v = n4; c5v = n5; c6v = n6; c7v = n7;
            s += 32;
        }

        if (have) {
            float xc = fmaf(sf, ddx, p0x);
            float yc = fmaf(sf, ddy, p0y);
            float zc = fmaf(sf, ddz, p0z);
            float ax = xc - floorf(xc);
            float ay = yc - floorf(yc);
            float az = zc - floorf(zc);

            float c00 = fmaf(az, c1v - c0v, c0v);
            float c01 = fmaf(az, c3v - c2v, c2v);
            float c10 = fmaf(az, c5v - c4v, c4v);
            float c11 = fmaf(az, c7v - c6v, c6v);
            float cc0 = fmaf(ay, c01 - c00, c00);
            float cc1 = fmaf(ay, c11 - c10, c10);
            acc += fmaf(ax, cc1 - cc0, cc0);
        }
    }

    // Warp reduction
    #pragma unroll
    for (int o = 16; o > 0; o >>= 1)
        acc += __shfl_down_sync(0xFFFFFFFFu, acc, o);

    if (lane == 0) out[blockIdx.x * PIX_PER_BLK + wid] = acc * step;
}

extern "C" void kernel_launch(void* const* d_in, const int* in_sizes, int n_in,
                              void* d_out, int out_size) {
    const float* vol    = (const float*)d_in[0];
    const float* k_inv  = (const float*)d_in[1];
    const float* rt_inv = (const float*)d_in[2];
    const float* sdd    = (const float*)d_in[3];
    const float* aff    = (const float*)d_in[4];
    const int*   n_ptr  = (const int*)d_in[5];
    float* out = (float*)d_out;

    // 4 pixels per 128-thread block (NPIX = 40000 divisible by 4).
    drr_kernel<<<NPIX / PIX_PER_BLK, MAIN_TPB>>>(vol, k_inv, rt_inv, sdd, aff, n_ptr, out);
}

// round 15
// speedup vs baseline: 1.1612x; 1.1612x over previous
#include <cuda_runtime.h>
#include <cuda_bf16.h>
#include <math.h>

// DRR raycast, two-phase:
//   Phase 1 (geom): 1 thread/pixel computes ray params + sample ranges -> scratch.
//   Phase 2 (main): 1 warp/pixel; lanes stride sample axis. Interior is
//   software-pipelined; fractions recomputed at consume time to keep live
//   registers at 32 -> full 64-warp occupancy via launch_bounds(128,16).
// Inputs (metadata order): volume[256^3] f32, k_inv[1,3,3], rt_inv[1,4,4],
//                          sdd[1], affine_inv[4,4], n_samples int32
// Output: f32 [1,200,200]

#define DRR_W 200
#define DRR_H 200
#define DRR_VOL 256
#define NPIX (DRR_W * DRR_H)

__device__ float4 g_geomA[NPIX];   // {p0x, p0y, p0z, step}
__device__ float4 g_geomB[NPIX];   // {ddx, ddy, ddz, 0}
__device__ int4   g_rng[NPIX];     // {s_lo, s_hi, A, B}

__device__ __forceinline__ void axis_clip(float p, float d, float lo_b, float hi_b,
                                          float& lo, float& hi) {
    if (fabsf(d) < 1e-12f) {
        if (p < lo_b || p > hi_b) { lo = 1.0f; hi = 0.0f; }
    } else {
        float r  = 1.0f / d;
        float ta = (lo_b - p) * r;
        float tb = (hi_b - p) * r;
        lo = fmaxf(lo, fminf(ta, tb));
        hi = fminf(hi, fmaxf(ta, tb));
    }
}

// ---------------- Phase 1: geometry, one thread per pixel ----------------
__global__ void drr_geom_kernel(const float* __restrict__ k_inv,
                                const float* __restrict__ rt_inv,
                                const float* __restrict__ sdd_p,
                                const float* __restrict__ aff,
                                const int*   __restrict__ n_ptr) {
    int pix = blockIdx.x * blockDim.x + threadIdx.x;
    if (pix >= NPIX) return;

    int u = pix % DRR_W;
    int v = pix / DRR_W;

    int   n    = *n_ptr;
    float fn1  = (float)(n - 1);
    float invn = 1.0f / fn1;
    float sdd  = __ldg(sdd_p);
    float fu = (float)u, fv = (float)v;

    float tc0 = (__ldg(k_inv + 0) * fu + __ldg(k_inv + 1) * fv + __ldg(k_inv + 2)) * sdd;
    float tc1 = (__ldg(k_inv + 3) * fu + __ldg(k_inv + 4) * fv + __ldg(k_inv + 5)) * sdd;
    float tc2 = (__ldg(k_inv + 6) * fu + __ldg(k_inv + 7) * fv + __ldg(k_inv + 8)) * sdd;

    float ray0 = __ldg(rt_inv + 0) * tc0 + __ldg(rt_inv + 1) * tc1 + __ldg(rt_inv + 2)  * tc2;
    float ray1 = __ldg(rt_inv + 4) * tc0 + __ldg(rt_inv + 5) * tc1 + __ldg(rt_inv + 6)  * tc2;
    float ray2 = __ldg(rt_inv + 8) * tc0 + __ldg(rt_inv + 9) * tc1 + __ldg(rt_inv + 10) * tc2;
    float sx = __ldg(rt_inv + 3), sy = __ldg(rt_inv + 7), sz = __ldg(rt_inv + 11);

    float step = sqrtf(ray0 * ray0 + ray1 * ray1 + ray2 * ray2) * invn;

    float p0x = __ldg(aff + 0) * sx + __ldg(aff + 1) * sy + __ldg(aff + 2)  * sz + __ldg(aff + 3);
    float p0y = __ldg(aff + 4) * sx + __ldg(aff + 5) * sy + __ldg(aff + 6)  * sz + __ldg(aff + 7);
    float p0z = __ldg(aff + 8) * sx + __ldg(aff + 9) * sy + __ldg(aff + 10) * sz + __ldg(aff + 11);
    float dx  = __ldg(aff + 0) * ray0 + __ldg(aff + 1) * ray1 + __ldg(aff + 2)  * ray2;
    float dy  = __ldg(aff + 4) * ray0 + __ldg(aff + 5) * ray1 + __ldg(aff + 6)  * ray2;
    float dz  = __ldg(aff + 8) * ray0 + __ldg(aff + 9) * ray1 + __ldg(aff + 10) * ray2;

    float lo = 0.0f, hi = 1.0f;
    axis_clip(p0x, dx, -1.0f, (float)DRR_VOL, lo, hi);
    axis_clip(p0y, dy, -1.0f, (float)DRR_VOL, lo, hi);
    axis_clip(p0z, dz, -1.0f, (float)DRR_VOL, lo, hi);

    float li = 0.0f, hii = 1.0f;
    axis_clip(p0x, dx, 0.0f, 254.99f, li, hii);
    axis_clip(p0y, dy, 0.0f, 254.99f, li, hii);
    axis_clip(p0z, dz, 0.0f, 254.99f, li, hii);

    int s_lo, s_hi, A, B;
    if (lo <= hi) {
        s_lo = (int)floorf(lo * fn1) - 2;
        s_hi = (int)ceilf(hi * fn1) + 2;
        if (s_lo < 0) s_lo = 0;
        if (s_hi > n - 1) s_hi = n - 1;

        if (li <= hii) {
            A = (int)ceilf(li * fn1) + 1;
            B = (int)floorf(hii * fn1) - 1;
            if (A < s_lo) A = s_lo;
            if (B > s_hi) B = s_hi;
            if (B < A) { A = s_hi + 1; B = s_hi; }
        } else {
            A = s_hi + 1; B = s_hi;
        }
    } else {
        s_lo = 0; s_hi = -1; A = 1; B = 0;
    }

    g_geomA[pix] = make_float4(p0x, p0y, p0z, step);
    g_geomB[pix] = make_float4(dx * invn, dy * invn, dz * invn, 0.0f);
    g_rng[pix]   = make_int4(s_lo, s_hi, A, B);
}

// ---------------- Phase 2: sampling, one warp per pixel ----------------
__device__ __forceinline__ float fetch_vox(const float* __restrict__ vol,
                                           int x, int y, int z) {
    if ((unsigned)x < (unsigned)DRR_VOL &&
        (unsigned)y < (unsigned)DRR_VOL &&
        (unsigned)z < (unsigned)DRR_VOL) {
        return __ldg(vol + (x << 16) + (y << 8) + z);
    }
    return 0.0f;
}

__device__ __forceinline__ float trilinear_guarded(const float* __restrict__ vol,
                                                   float x, float y, float z) {
    float fx = floorf(x), fy = floorf(y), fz = floorf(z);
    int ix = (int)fx, iy = (int)fy, iz = (int)fz;
    float ax = x - fx, ay = y - fy, az = z - fz;

    float c000 = fetch_vox(vol, ix,     iy,     iz);
    float c001 = fetch_vox(vol, ix,     iy,     iz + 1);
    float c010 = fetch_vox(vol, ix,     iy + 1, iz);
    float c011 = fetch_vox(vol, ix,     iy + 1, iz + 1);
    float c100 = fetch_vox(vol, ix + 1, iy,     iz);
    float c101 = fetch_vox(vol, ix + 1, iy,     iz + 1);
    float c110 = fetch_vox(vol, ix + 1, iy + 1, iz);
    float c111 = fetch_vox(vol, ix + 1, iy + 1, iz + 1);

    float c00 = fmaf(az, c001 - c000, c000);
    float c01 = fmaf(az, c011 - c010, c010);
    float c10 = fmaf(az, c101 - c100, c100);
    float c11 = fmaf(az, c111 - c110, c110);
    float c0  = fmaf(ay, c01 - c00, c00);
    float c1  = fmaf(ay, c11 - c10, c10);
    return fmaf(ax, c1 - c0, c0);
}

#define MAIN_TPB 128

// (128,16): reg cap 32 (kernel already compiles to 32) -> 64 warps/SM, 100% occ.
__global__ __launch_bounds__(MAIN_TPB, 16)
void drr_main_kernel(const float* __restrict__ vol,
                     float* __restrict__ out) {
    int gwarp = (blockIdx.x * blockDim.x + threadIdx.x) >> 5;
    int lane  = threadIdx.x & 31;
    if (gwarp >= NPIX) return;

    float4 ga = __ldg(&g_geomA[gwarp]);
    float4 gb = __ldg(&g_geomB[gwarp]);
    int4   rg = __ldg(&g_rng[gwarp]);

    float p0x = ga.x, p0y = ga.y, p0z = ga.z, step = ga.w;
    float ddx = gb.x, ddy = gb.y, ddz = gb.z;
    int s_lo = rg.x, s_hi = rg.y, A = rg.z, B = rg.w;

    float acc = 0.0f;

    // --- Merged guarded boundary loop: head [s_lo, A-1] ++ tail [B+1, s_hi] ---
    {
        int headN = A - s_lo;
        int total = headN + (s_hi - B);
        #pragma unroll 1
        for (int k = lane; k < total; k += 32) {
            int s = (k < headN) ? (s_lo + k) : (B + 1 + (k - headN));
            float sf = (float)s;
            acc += trilinear_guarded(vol,
                                     fmaf(sf, ddx, p0x),
                                     fmaf(sf, ddy, p0y),
                                     fmaf(sf, ddz, p0z));
        }
    }

    // --- Unguarded interior [A, B], 2-stage pipeline, minimal live state ---
    // Cross-stage carry: sf + 8 loaded corner values. Fractions recomputed at
    // consume time: ax = x - floor(x) (identical bits to the int path since
    // interior coords are positive).
    {
        int s = A + lane;
        float sf;
        float c0v, c1v, c2v, c3v, c4v, c5v, c6v, c7v;

        bool have = (s <= B);
        if (have) {
            sf = (float)s;
            float x = fmaf(sf, ddx, p0x);
            float y = fmaf(sf, ddy, p0y);
            float z = fmaf(sf, ddz, p0z);
            int ix = __float2int_rd(x), iy = __float2int_rd(y), iz = __float2int_rd(z);
            const float* p = vol + (ix << 16) + (iy << 8) + iz;
            c0v = __ldg(p);         c1v = __ldg(p + 1);
            c2v = __ldg(p + 256);   c3v = __ldg(p + 257);
            c4v = __ldg(p + 65536); c5v = __ldg(p + 65537);
            c6v = __ldg(p + 65792); c7v = __ldg(p + 65793);
        }

        #pragma unroll 1
        while (s + 32 <= B) {
            // Prefetch next batch (independent of current lerp chain).
            float sfn = sf + 32.0f;
            float xn = fmaf(sfn, ddx, p0x);
            float yn = fmaf(sfn, ddy, p0y);
            float zn = fmaf(sfn, ddz, p0z);
            int ixn = __float2int_rd(xn), iyn = __float2int_rd(yn), izn = __float2int_rd(zn);
            const float* pn = vol + (ixn << 16) + (iyn << 8) + izn;
            float n0 = __ldg(pn);         float n1 = __ldg(pn + 1);
            float n2 = __ldg(pn + 256);   float n3 = __ldg(pn + 257);
            float n4 = __ldg(pn + 65536); float n5 = __ldg(pn + 65537);
            float n6 = __ldg(pn + 65792); float n7 = __ldg(pn + 65793);

            // Consume current batch; fractions recomputed from sf.
            float xc = fmaf(sf, ddx, p0x);
            float yc = fmaf(sf, ddy, p0y);
            float zc = fmaf(sf, ddz, p0z);
            float ax = xc - floorf(xc);
            float ay = yc - floorf(yc);
            float az = zc - floorf(zc);

            float c00 = fmaf(az, c1v - c0v, c0v);
            float c01 = fmaf(az, c3v - c2v, c2v);
            float c10 = fmaf(az, c5v - c4v, c4v);
            float c11 = fmaf(az, c7v - c6v, c6v);
            float cc0 = fmaf(ay, c01 - c00, c00);
            float cc1 = fmaf(ay, c11 - c10, c10);
            acc += fmaf(ax, cc1 - cc0, cc0);

            // Rotate pipeline.
            sf = sfn;
            c0v = n0; c1v = n1; c2v = n2; c3v = n3;
            c4v = n4; c5v = n5; c6v = n6; c7v = n7;
            s += 32;
        }

        if (have) {
            float xc = fmaf(sf, ddx, p0x);
            float yc = fmaf(sf, ddy, p0y);
            float zc = fmaf(sf, ddz, p0z);
            float ax = xc - floorf(xc);
            float ay = yc - floorf(yc);
            float az = zc - floorf(zc);

            float c00 = fmaf(az, c1v - c0v, c0v);
            float c01 = fmaf(az, c3v - c2v, c2v);
            float c10 = fmaf(az, c5v - c4v, c4v);
            float c11 = fmaf(az, c7v - c6v, c6v);
            float cc0 = fmaf(ay, c01 - c00, c00);
            float cc1 = fmaf(ay, c11 - c10, c10);
            acc += fmaf(ax, cc1 - cc0, cc0);
        }
    }

    // Warp reduction
    #pragma unroll
    for (int o = 16; o > 0; o >>= 1)
        acc += __shfl_down_sync(0xFFFFFFFFu, acc, o);

    if (lane == 0) out[gwarp] = acc * step;
}

extern "C" void kernel_launch(void* const* d_in, const int* in_sizes, int n_in,
                              void* d_out, int out_size) {
    const float* vol    = (const float*)d_in[0];
    const float* k_inv  = (const float*)d_in[1];
    const float* rt_inv = (const float*)d_in[2];
    const float* sdd    = (const float*)d_in[3];
    const float* aff    = (const float*)d_in[4];
    const int*   n_ptr  = (const int*)d_in[5];
    float* out = (float*)d_out;

    drr_geom_kernel<<<(NPIX + 255) / 256, 256>>>(k_inv, rt_inv, sdd, aff, n_ptr);

    int blocks = (NPIX * 32 + MAIN_TPB - 1) / MAIN_TPB;
    drr_main_kernel<<<blocks, MAIN_TPB>>>(vol, out);
}